// round 16
// baseline (speedup 1.0000x reference)
#include <cuda_runtime.h>
#include <cuda_bf16.h>
#include <math.h>

#define NN_ 768
#define CC_ 768
#define CS_ 384
#define HH_ 16
#define FF_ 1536
#define LL_ 8
#define NC_ (NN_*CC_)
#define NNSQ_ 589824LL
#define NSPLIT_ 2

// ---------------- scratch ----------------
__device__ static __nv_bfloat16 g_pl[LL_*HH_*NN_*NN_];
__device__ static __nv_bfloat16 g_pwh[2*8192];
__device__ static __nv_bfloat16 g_x[NC_];
__device__ static __nv_bfloat16 g_q[NC_], g_k[NC_], g_v[NC_], g_gate[NC_], g_wa[NC_];
__device__ static __nv_bfloat16 g_u[NN_*2*FF_];
__device__ static float g_opart[NSPLIT_*HH_*NN_*48];
__device__ static float g_ml[NSPLIT_*HH_*NN_*2];
__device__ static float g_lnsc[NN_*CS_];
__device__ static float g_cnA[LL_*NN_*CS_], g_cnF[LL_*NN_*CS_];
__device__ static float g_sigA[LL_*NC_], g_addA[LL_*NC_], g_azcA[LL_*NC_];
__device__ static float g_sigF[LL_*NC_], g_addF[LL_*NC_], g_azcF[LL_*NC_];
__device__ static float g_bias[NN_];

// ---------------- bf16 mma helpers ----------------
__device__ __forceinline__ unsigned f2bf2(float lo, float hi){
    unsigned r; asm("cvt.rn.bf16x2.f32 %0, %1, %2;" : "=r"(r) : "f"(hi), "f"(lo)); return r;
}
__device__ __forceinline__ unsigned s2u(const void* p){
    return (unsigned)__cvta_generic_to_shared(p);
}
__device__ __forceinline__ void ldsm4(unsigned* r, unsigned a){
    asm volatile("ldmatrix.sync.aligned.m8n8.x4.shared.b16 {%0,%1,%2,%3}, [%4];"
        : "=r"(r[0]),"=r"(r[1]),"=r"(r[2]),"=r"(r[3]) : "r"(a));
}
__device__ __forceinline__ void ldsm2(unsigned* r, unsigned a){
    asm volatile("ldmatrix.sync.aligned.m8n8.x2.shared.b16 {%0,%1}, [%2];"
        : "=r"(r[0]),"=r"(r[1]) : "r"(a));
}
__device__ __forceinline__ void ldsm2t(unsigned* r, unsigned a){
    asm volatile("ldmatrix.sync.aligned.m8n8.x2.trans.shared.b16 {%0,%1}, [%2];"
        : "=r"(r[0]),"=r"(r[1]) : "r"(a));
}
__device__ __forceinline__ void ldsm4t(unsigned* r, unsigned a){
    asm volatile("ldmatrix.sync.aligned.m8n8.x4.trans.shared.b16 {%0,%1,%2,%3}, [%4];"
        : "=r"(r[0]),"=r"(r[1]),"=r"(r[2]),"=r"(r[3]) : "r"(a));
}
__device__ __forceinline__ void mma_bf16(float* c, const unsigned* a, const unsigned* b){
    asm volatile("mma.sync.aligned.m16n8k16.row.col.f32.bf16.bf16.f32 "
        "{%0,%1,%2,%3}, {%4,%5,%6,%7}, {%8,%9}, {%0,%1,%2,%3};"
        : "+f"(c[0]),"+f"(c[1]),"+f"(c[2]),"+f"(c[3])
        : "r"(a[0]),"r"(a[1]),"r"(a[2]),"r"(a[3]),"r"(b[0]),"r"(b[1]));
}

// ---------------- reductions ----------------
__device__ __forceinline__ float blockReduce(float v, float* red, bool ismax){
    __syncthreads();
    int lane = threadIdx.x & 31, w = threadIdx.x >> 5, nw = blockDim.x >> 5;
    #pragma unroll
    for (int o = 16; o; o >>= 1){
        float u = __shfl_xor_sync(0xffffffffu, v, o);
        v = ismax ? fmaxf(v, u) : v + u;
    }
    if (lane == 0) red[w] = v;
    __syncthreads();
    if (w == 0){
        v = (lane < nw) ? red[lane] : (ismax ? -1e30f : 0.f);
        #pragma unroll
        for (int o = 16; o; o >>= 1){
            float u = __shfl_xor_sync(0xffffffffu, v, o);
            v = ismax ? fmaxf(v, u) : v + u;
        }
        if (lane == 0) red[0] = v;
    }
    __syncthreads();
    return red[0];
}

// ---------------- epilogue value transform ----------------
__device__ __forceinline__ float epv(int mode, const float* P1, int n, float r){
    if (mode == 1) return r + P1[n];
    if (mode == 2) return 1.f / (1.f + __expf(-(r + P1[n])));
    return r;
}

// ---------------- GLU on a uint4 pair of bf16x8 ----------------
__device__ __forceinline__ uint4 glu8(uint4 u1, uint4 u2){
    const __nv_bfloat162* p1 = (const __nv_bfloat162*)&u1;
    const __nv_bfloat162* p2 = (const __nv_bfloat162*)&u2;
    uint4 out;
    unsigned* po = &out.x;
    #pragma unroll
    for (int j = 0; j < 4; j++){
        float2 a = __bfloat1622float2(p1[j]);
        float2 b = __bfloat1622float2(p2[j]);
        float c0 = (a.x/(1.f+__expf(-a.x)))*b.x;
        float c1 = (a.y/(1.f+__expf(-a.y)))*b.y;
        po[j] = f2bf2(c0, c1);
    }
    return out;
}

// ---------------- bf16 GEMM body: MROWSx64 tile, BK=32, 256 thr, double-buffered ----------------
// GLU=1 (requires ABF=1): logical A[m][k] = swish(u[m][k]) * u[m][k+1536]; lda = raw u width.
template<int MROWS, int ABF, int CBF, int GLU>
__device__ __forceinline__ void gemm_body(int K,
    const void* __restrict__ Av, int lda,
    const float* __restrict__ B, int ldb,
    void* __restrict__ Cv, int ldc,
    int mode, const float* __restrict__ P1,
    __nv_bfloat16* Asb, __nv_bfloat16* Bsb)
{
    const float* Af = (const float*)Av;
    const __nv_bfloat16* Ah = (const __nv_bfloat16*)Av;
    constexpr int MH  = MROWS / 2;
    constexpr int NMT = MH / 16;
    constexpr int NAC = MROWS / 32;

    int bm = blockIdx.y * MROWS, bn = blockIdx.x << 6;
    int t = threadIdx.x, lane = t & 31, w = t >> 5;
    int wm = w & 1, wn = w >> 1;
    int a_r = t >> 3, a_c = (t & 7) << 2;
    int a8_r = t >> 2, a8_c = (t & 3) << 3;
    int b_r = t >> 4, b_c = (t & 15) << 2;
    int arow = ((lane >> 3) & 1) * 8 + (lane & 7);
    int acol = (lane >> 4) << 3;
    bool a8on = (a8_r < MROWS);

    float acc[NMT][2][4];
    #pragma unroll
    for (int i = 0; i < NMT; i++)
        #pragma unroll
        for (int j = 0; j < 2; j++)
            #pragma unroll
            for (int q = 0; q < 4; q++) acc[i][j][q] = 0.f;

    float4 raf[NAC]; uint4 rah, rah2;
    if (ABF){
        if (a8on){
            rah = *(const uint4*)&Ah[(long long)(bm + a8_r)*lda + a8_c];
            if (GLU) rah2 = *(const uint4*)&Ah[(long long)(bm + a8_r)*lda + FF_ + a8_c];
        }
    } else {
        #pragma unroll
        for (int i = 0; i < NAC; i++)
            raf[i] = *(const float4*)&Af[(long long)(bm + a_r + 32*i)*lda + a_c];
    }
    float4 rb0 = *(const float4*)&B[(long long)b_r*ldb + bn + b_c];
    float4 rb1 = *(const float4*)&B[(long long)(b_r + 16)*ldb + bn + b_c];

    int nk = K >> 5;
    for (int it = 0;;){
        __nv_bfloat16* As = Asb + (it & 1) * (MROWS*40);
        __nv_bfloat16* Bs = Bsb + (it & 1) * (32*72);
        uint2 u;
        if (ABF){
            if (a8on){
                if (GLU) *(uint4*)&As[a8_r*40 + a8_c] = glu8(rah, rah2);
                else     *(uint4*)&As[a8_r*40 + a8_c] = rah;
            }
        } else {
            #pragma unroll
            for (int i = 0; i < NAC; i++){
                u.x = f2bf2(raf[i].x, raf[i].y); u.y = f2bf2(raf[i].z, raf[i].w);
                *(uint2*)&As[(a_r + 32*i)*40 + a_c] = u;
            }
        }
        u.x = f2bf2(rb0.x, rb0.y); u.y = f2bf2(rb0.z, rb0.w);
        *(uint2*)&Bs[b_r*72 + b_c] = u;
        u.x = f2bf2(rb1.x, rb1.y); u.y = f2bf2(rb1.z, rb1.w);
        *(uint2*)&Bs[(b_r + 16)*72 + b_c] = u;
        __syncthreads();

        int itn = it + 1;
        if (itn < nk){
            int k1 = itn << 5;
            if (ABF){
                if (a8on){
                    rah = *(const uint4*)&Ah[(long long)(bm + a8_r)*lda + k1 + a8_c];
                    if (GLU) rah2 = *(const uint4*)&Ah[(long long)(bm + a8_r)*lda + FF_ + k1 + a8_c];
                }
            } else {
                #pragma unroll
                for (int i = 0; i < NAC; i++)
                    raf[i] = *(const float4*)&Af[(long long)(bm + a_r + 32*i)*lda + k1 + a_c];
            }
            rb0 = *(const float4*)&B[(long long)(k1 + b_r)*ldb + bn + b_c];
            rb1 = *(const float4*)&B[(long long)(k1 + b_r + 16)*ldb + bn + b_c];
        }

        unsigned aB = s2u(As), bB = s2u(Bs);
        #pragma unroll
        for (int k16 = 0; k16 < 32; k16 += 16){
            unsigned af[NMT][4], bf[2][2];
            #pragma unroll
            for (int mt = 0; mt < NMT; mt++)
                ldsm4(af[mt], aB + ((wm*MH + mt*16 + arow)*40 + k16 + acol)*2);
            #pragma unroll
            for (int nt = 0; nt < 2; nt++)
                ldsm2t(bf[nt], bB + ((k16 + (lane & 15))*72 + wn*16 + nt*8)*2);
            #pragma unroll
            for (int mt = 0; mt < NMT; mt++)
                #pragma unroll
                for (int nt = 0; nt < 2; nt++)
                    mma_bf16(acc[mt][nt], af[mt], bf[nt]);
        }
        it = itn;
        if (it >= nk) break;
    }

    #pragma unroll
    for (int mt = 0; mt < NMT; mt++){
        int r0 = bm + wm*MH + mt*16 + (lane >> 2);
        #pragma unroll
        for (int nt = 0; nt < 2; nt++){
            int c0 = bn + wn*16 + nt*8 + 2*(lane & 3);
            float* ac = acc[mt][nt];
            if (CBF){
                __nv_bfloat16* Ch = (__nv_bfloat16*)Cv;
                *(unsigned*)&Ch[(long long)r0*ldc + c0] =
                    f2bf2(epv(mode, P1, c0, ac[0]), epv(mode, P1, c0+1, ac[1]));
                *(unsigned*)&Ch[(long long)(r0+8)*ldc + c0] =
                    f2bf2(epv(mode, P1, c0, ac[2]), epv(mode, P1, c0+1, ac[3]));
            } else {
                float* Cf = (float*)Cv;
                long long ci0 = (long long)r0*ldc + c0;
                long long ci1 = (long long)(r0+8)*ldc + c0;
                if (mode == 4){
                    Cf[ci0]   += P1[ci0]   * ac[0];
                    Cf[ci0+1] += P1[ci0+1] * ac[1];
                    Cf[ci1]   += P1[ci1]   * ac[2];
                    Cf[ci1+1] += P1[ci1+1] * ac[3];
                } else {
                    Cf[ci0]   = epv(mode, P1, c0,   ac[0]);
                    Cf[ci0+1] = epv(mode, P1, c0+1, ac[1]);
                    Cf[ci1]   = epv(mode, P1, c0,   ac[2]);
                    Cf[ci1+1] = epv(mode, P1, c0+1, ac[3]);
                }
            }
        }
    }
}

template<int MROWS, int ABF, int CBF, int GLU>
__global__ void gemm_tc(int K,
    const void* __restrict__ A, int lda, long long sA,
    const float* __restrict__ B, int ldb, long long sB,
    void* __restrict__ C, int ldc, long long sC,
    int mode, const float* __restrict__ P1, long long sP1)
{
    __shared__ __align__(16) __nv_bfloat16 As[2*MROWS*40];
    __shared__ __align__(16) __nv_bfloat16 Bs[2*32*72];
    int bz = blockIdx.z;
    const void* Ab = ABF ? (const void*)((const __nv_bfloat16*)A + (long long)bz*sA)
                         : (const void*)((const float*)A + (long long)bz*sA);
    void* Cb = CBF ? (void*)((__nv_bfloat16*)C + (long long)bz*sC)
                   : (void*)((float*)C + (long long)bz*sC);
    gemm_body<MROWS,ABF,CBF,GLU>(K, Ab, lda, B + (long long)bz*sB, ldb, Cb, ldc, mode,
                P1 ? P1 + (long long)bz*sP1 : P1, As, Bs);
}

// all 6 conditioning precompute GEMMs in one launch (grid.z = 48; z/8 selects config)
__global__ void pre6_tc(const float* __restrict__ cnA, const float* __restrict__ cnF,
    const float* __restrict__ sc,
    const float* __restrict__ csA, const float* __restrict__ cbA, const float* __restrict__ azA,
    const float* __restrict__ csF, const float* __restrict__ cbF, const float* __restrict__ azF,
    float* __restrict__ sigA, float* __restrict__ addA, float* __restrict__ azcA,
    float* __restrict__ sigF, float* __restrict__ addF, float* __restrict__ azcF,
    const float* __restrict__ csbA, const float* __restrict__ azbA,
    const float* __restrict__ csbF, const float* __restrict__ azbF)
{
    __shared__ __align__(16) __nv_bfloat16 As[2*64*40];
    __shared__ __align__(16) __nv_bfloat16 Bs[2*32*72];
    int g = blockIdx.z >> 3, bz = blockIdx.z & 7;
    const float* A; const float* B; float* C; int mode; const float* P1; long long sA;
    switch (g){
        case 0: A = cnA; sA = (long long)NN_*CS_; B = csA; C = sigA; mode = 2; P1 = csbA; break;
        case 1: A = cnA; sA = (long long)NN_*CS_; B = cbA; C = addA; mode = 0; P1 = 0;    break;
        case 2: A = sc;  sA = 0;                  B = azA; C = azcA; mode = 2; P1 = azbA; break;
        case 3: A = cnF; sA = (long long)NN_*CS_; B = csF; C = sigF; mode = 2; P1 = csbF; break;
        case 4: A = cnF; sA = (long long)NN_*CS_; B = cbF; C = addF; mode = 0; P1 = 0;    break;
        default:A = sc;  sA = 0;                  B = azF; C = azcF; mode = 2; P1 = azbF; break;
    }
    A += (long long)bz * sA;
    B += (long long)bz * CS_ * CC_;
    C += (long long)bz * NC_;
    if (P1) P1 += bz * 768;
    gemm_body<64,0,0,0>(384, A, 384, B, 768, (void*)C, 768, mode, P1, As, Bs);
}

// fused QKV+gate: A bf16, outputs bf16 (64-row tiles)
__global__ void qkvg_tc(const __nv_bfloat16* __restrict__ A,
    const float* __restrict__ Bq, const float* __restrict__ Bk,
    const float* __restrict__ Bv, const float* __restrict__ Bg,
    __nv_bfloat16* __restrict__ Cq, __nv_bfloat16* __restrict__ Ck,
    __nv_bfloat16* __restrict__ Cv, __nv_bfloat16* __restrict__ Cg,
    const float* __restrict__ biasq, const float* __restrict__ biasg)
{
    __shared__ __align__(16) __nv_bfloat16 As[2*64*40];
    __shared__ __align__(16) __nv_bfloat16 Bs[2*32*72];
    int z = blockIdx.z;
    const float* B = (z==0) ? Bq : (z==1) ? Bk : (z==2) ? Bv : Bg;
    __nv_bfloat16* C = (z==0) ? Cq : (z==1) ? Ck : (z==2) ? Cv : Cg;
    int mode       = (z==0) ? 1 : (z==3) ? 2 : 0;
    const float* P1= (z==0) ? biasq : (z==3) ? biasg : (const float*)0;
    gemm_body<64,1,1,0>(768, A, 768, B, 768, (void*)C, 768, mode, P1, As, Bs);
}

// ---------------- flash, split-kv: grid (16,12,NSPLIT_); each part does 12/NSPLIT_ kv tiles ----------------
__global__ void flash_k(const __nv_bfloat16* __restrict__ qg, const __nv_bfloat16* __restrict__ kg,
                        const __nv_bfloat16* __restrict__ vg,
                        const __nv_bfloat16* __restrict__ plg)
{
    extern __shared__ __align__(16) char fsm[];
    __nv_bfloat16* Qs   = (__nv_bfloat16*)fsm;   // 64x56
    __nv_bfloat16* Ks   = Qs + 64*56;            // 2 x 64x56
    __nv_bfloat16* Vs   = Ks + 2*64*56;          // 2 x 64x56
    __nv_bfloat16* plsh = Vs + 2*64*56;          // 2 x 64x72
    float* bias_s = (float*)(plsh + 2*64*72);    // 768
    float* redm   = bias_s + 768;                // 2x64
    float* reds   = redm + 128;                  // 2x64
    float* Of     = (float*)plsh;                // reused after loop (64x52)

    const float scale = 0.14433756729740643f;
    int h = blockIdx.x, q0 = blockIdx.y * 64;
    int z = blockIdx.z;
    int ktlo = z*(12/NSPLIT_), kthi = ktlo + (12/NSPLIT_);
    int t = threadIdx.x, lane = t & 31, w = t >> 5;
    int wm = w & 3, wn = w >> 2;
    int r0l = wm*16 + (lane >> 2), r1l = r0l + 8;
    int arow = ((lane >> 3) & 1) * 8 + (lane & 7);
    int acol = (lane >> 4) << 3;

    int kv_r0 = t / 6,        kv_c0 = (t % 6) * 8;
    int kv_r1 = (t + 256)/6,  kv_c1 = ((t + 256) % 6) * 8;
    bool kv2 = (t < 128);
    int pl_r0 = t >> 3,          pl_c0 = (t & 7) * 8;
    int pl_r1 = (t + 256) >> 3,  pl_c1 = ((t + 256) & 7) * 8;

    // stage Q + bias + first tile of this part (into local buffer 0)
    for (int i = t; i < 384; i += 256){
        int r = i / 6, c8 = (i % 6) * 8;
        *(uint4*)&Qs[r*56 + c8] = *(const uint4*)&qg[(long long)(q0 + r)*768 + h*48 + c8];
    }
    for (int i = t; i < 768; i += 256) bias_s[i] = g_bias[i];
    {
        int kb0 = ktlo * 64;
        *(uint4*)&Ks[kv_r0*56 + kv_c0] = *(const uint4*)&kg[(long long)(kb0 + kv_r0)*768 + h*48 + kv_c0];
        *(uint4*)&Vs[kv_r0*56 + kv_c0] = *(const uint4*)&vg[(long long)(kb0 + kv_r0)*768 + h*48 + kv_c0];
        if (kv2){
            *(uint4*)&Ks[kv_r1*56 + kv_c1] = *(const uint4*)&kg[(long long)(kb0 + kv_r1)*768 + h*48 + kv_c1];
            *(uint4*)&Vs[kv_r1*56 + kv_c1] = *(const uint4*)&vg[(long long)(kb0 + kv_r1)*768 + h*48 + kv_c1];
        }
        *(uint4*)&plsh[pl_r0*72 + pl_c0] = *(const uint4*)&plg[((long long)h*768 + q0 + pl_r0)*768 + kb0 + pl_c0];
        *(uint4*)&plsh[pl_r1*72 + pl_c1] = *(const uint4*)&plg[((long long)h*768 + q0 + pl_r1)*768 + kb0 + pl_c1];
    }
    __syncthreads();
    unsigned qB = s2u(Qs);
    unsigned aq[3][4];
    #pragma unroll
    for (int kk = 0; kk < 3; kk++)
        ldsm4(aq[kk], qB + ((wm*16 + arow)*56 + kk*16 + acol)*2);

    float m0o = -1e30f, m1o = -1e30f, l0 = 0.f, l1 = 0.f;
    float acc[6][4];
    #pragma unroll
    for (int i = 0; i < 6; i++)
        #pragma unroll
        for (int q = 0; q < 4; q++) acc[i][q] = 0.f;

    for (int kt = ktlo; kt < kthi; kt++){
        int buf = (kt - ktlo) & 1;
        __nv_bfloat16* Kb = Ks + buf*(64*56);
        __nv_bfloat16* Vb = Vs + buf*(64*56);
        __nv_bfloat16* Pb = plsh + buf*(64*72);
        unsigned kB = s2u(Kb), vB = s2u(Vb);
        int k0 = kt * 64;

        uint4 pk0, pk1, pv0, pv1, pp0, pp1;
        if (kt + 1 < kthi){
            int k1 = k0 + 64;
            pk0 = *(const uint4*)&kg[(long long)(k1 + kv_r0)*768 + h*48 + kv_c0];
            pv0 = *(const uint4*)&vg[(long long)(k1 + kv_r0)*768 + h*48 + kv_c0];
            if (kv2){
                pk1 = *(const uint4*)&kg[(long long)(k1 + kv_r1)*768 + h*48 + kv_c1];
                pv1 = *(const uint4*)&vg[(long long)(k1 + kv_r1)*768 + h*48 + kv_c1];
            }
            pp0 = *(const uint4*)&plg[((long long)h*768 + q0 + pl_r0)*768 + k1 + pl_c0];
            pp1 = *(const uint4*)&plg[((long long)h*768 + q0 + pl_r1)*768 + k1 + pl_c1];
        }

        float s[4][4];
        #pragma unroll
        for (int i = 0; i < 4; i++)
            #pragma unroll
            for (int q = 0; q < 4; q++) s[i][q] = 0.f;
        #pragma unroll
        for (int kk = 0; kk < 3; kk++){
            #pragma unroll
            for (int nt = 0; nt < 4; nt++){
                unsigned bk[2];
                ldsm2(bk, kB + ((wn*32 + nt*8 + (lane & 7))*56 + kk*16 + (lane & 8))*2);
                mma_bf16(s[nt], aq[kk], bk);
            }
        }
        float rm0 = -1e30f, rm1 = -1e30f;
        #pragma unroll
        for (int nt = 0; nt < 4; nt++){
            int c = wn*32 + nt*8 + 2*(lane & 3);
            float2 b  = *(float2*)&bias_s[k0 + c];
            float2 p0 = __bfloat1622float2(*(const __nv_bfloat162*)&Pb[r0l*72 + c]);
            float2 p1 = __bfloat1622float2(*(const __nv_bfloat162*)&Pb[r1l*72 + c]);
            s[nt][0] = fmaf(s[nt][0], scale, p0.x + b.x);
            s[nt][1] = fmaf(s[nt][1], scale, p0.y + b.y);
            s[nt][2] = fmaf(s[nt][2], scale, p1.x + b.x);
            s[nt][3] = fmaf(s[nt][3], scale, p1.y + b.y);
            rm0 = fmaxf(rm0, fmaxf(s[nt][0], s[nt][1]));
            rm1 = fmaxf(rm1, fmaxf(s[nt][2], s[nt][3]));
        }
        rm0 = fmaxf(rm0, __shfl_xor_sync(0xffffffffu, rm0, 1));
        rm0 = fmaxf(rm0, __shfl_xor_sync(0xffffffffu, rm0, 2));
        rm1 = fmaxf(rm1, __shfl_xor_sync(0xffffffffu, rm1, 1));
        rm1 = fmaxf(rm1, __shfl_xor_sync(0xffffffffu, rm1, 2));
        if ((lane & 3) == 0){ redm[wn*64 + r0l] = rm0; redm[wn*64 + r1l] = rm1; }
        __syncthreads();
        float m0 = fmaxf(m0o, fmaxf(redm[r0l], redm[64 + r0l]));
        float m1 = fmaxf(m1o, fmaxf(redm[r1l], redm[64 + r1l]));
        float sc0 = __expf(m0o - m0), sc1 = __expf(m1o - m1);
        m0o = m0; m1o = m1;
        float rs0 = 0.f, rs1 = 0.f;
        #pragma unroll
        for (int nt = 0; nt < 4; nt++){
            s[nt][0] = __expf(s[nt][0] - m0);
            s[nt][1] = __expf(s[nt][1] - m0);
            s[nt][2] = __expf(s[nt][2] - m1);
            s[nt][3] = __expf(s[nt][3] - m1);
            rs0 += s[nt][0] + s[nt][1];
            rs1 += s[nt][2] + s[nt][3];
        }
        rs0 += __shfl_xor_sync(0xffffffffu, rs0, 1);
        rs0 += __shfl_xor_sync(0xffffffffu, rs0, 2);
        rs1 += __shfl_xor_sync(0xffffffffu, rs1, 1);
        rs1 += __shfl_xor_sync(0xffffffffu, rs1, 2);
        if ((lane & 3) == 0){ reds[wn*64 + r0l] = rs0; reds[wn*64 + r1l] = rs1; }
        #pragma unroll
        for (int nt = 0; nt < 6; nt++){
            acc[nt][0] *= sc0; acc[nt][1] *= sc0;
            acc[nt][2] *= sc1; acc[nt][3] *= sc1;
        }
        __syncthreads();
        l0 = l0 * sc0 + reds[r0l] + reds[64 + r0l];
        l1 = l1 * sc1 + reds[r1l] + reds[64 + r1l];
        #pragma unroll
        for (int c16 = 0; c16 < 2; c16++){
            unsigned ap[4];
            ap[0] = f2bf2(s[2*c16  ][0], s[2*c16  ][1]);
            ap[1] = f2bf2(s[2*c16  ][2], s[2*c16  ][3]);
            ap[2] = f2bf2(s[2*c16+1][0], s[2*c16+1][1]);
            ap[3] = f2bf2(s[2*c16+1][2], s[2*c16+1][3]);
            #pragma unroll
            for (int nt = 0; nt < 6; nt++){
                unsigned bv[2];
                ldsm2t(bv, vB + ((wn*32 + c16*16 + (lane & 15))*56 + nt*8)*2);
                mma_bf16(acc[nt], ap, bv);
            }
        }
        if (kt + 1 < kthi){
            __nv_bfloat16* Kn = Ks + (buf^1)*(64*56);
            __nv_bfloat16* Vn = Vs + (buf^1)*(64*56);
            __nv_bfloat16* Pn = plsh + (buf^1)*(64*72);
            *(uint4*)&Kn[kv_r0*56 + kv_c0] = pk0;
            *(uint4*)&Vn[kv_r0*56 + kv_c0] = pv0;
            if (kv2){
                *(uint4*)&Kn[kv_r1*56 + kv_c1] = pk1;
                *(uint4*)&Vn[kv_r1*56 + kv_c1] = pv1;
            }
            *(uint4*)&Pn[pl_r0*72 + pl_c0] = pp0;
            *(uint4*)&Pn[pl_r1*72 + pl_c1] = pp1;
            __syncthreads();
        }
    }

    // merge the two kv-quarter (wn) partial O's; write unnormalized partial + (m,l)
    __syncthreads();
    if (wn == 1){
        #pragma unroll
        for (int nt = 0; nt < 6; nt++){
            int c = nt*8 + 2*(lane & 3);
            *(float2*)&Of[r0l*52 + c] = make_float2(acc[nt][0], acc[nt][1]);
            *(float2*)&Of[r1l*52 + c] = make_float2(acc[nt][2], acc[nt][3]);
        }
    }
    __syncthreads();
    if (wn == 0){
        long long base = ((long long)(z*HH_ + h)*NN_ + q0);
        #pragma unroll
        for (int nt = 0; nt < 6; nt++){
            int c = nt*8 + 2*(lane & 3);
            float2 o0 = *(float2*)&Of[r0l*52 + c];
            float2 o1 = *(float2*)&Of[r1l*52 + c];
            *(float2*)&g_opart[(base + r0l)*48 + c] =
                make_float2(acc[nt][0] + o0.x, acc[nt][1] + o0.y);
            *(float2*)&g_opart[(base + r1l)*48 + c] =
                make_float2(acc[nt][2] + o1.x, acc[nt][3] + o1.y);
        }
        if ((lane & 3) == 0){
            g_ml[(base + r0l)*2    ] = m0o;
            g_ml[(base + r0l)*2 + 1] = l0;
            g_ml[(base + r1l)*2    ] = m1o;
            g_ml[(base + r1l)*2 + 1] = l1;
        }
    }
}

// combine the NSPLIT_ kv parts: softmax merge + gate, bf16 out
__global__ void comb_k(const __nv_bfloat16* __restrict__ gateg, __nv_bfloat16* __restrict__ og){
    int row = blockIdx.x, tid = threadIdx.x;      // 384 threads
    int h = tid / 24, c = (tid % 24) * 2;
    long long idx[NSPLIT_];
    float mz[NSPLIT_], lz[NSPLIT_];
    float m = -1e30f;
    #pragma unroll
    for (int p = 0; p < NSPLIT_; p++){
        idx[p] = (long long)(p*HH_ + h)*NN_ + row;
        mz[p] = g_ml[idx[p]*2];
        lz[p] = g_ml[idx[p]*2 + 1];
        m = fmaxf(m, mz[p]);
    }
    float den = 0.f;
    float wz[NSPLIT_];
    #pragma unroll
    for (int p = 0; p < NSPLIT_; p++){
        wz[p] = __expf(mz[p] - m);
        den += lz[p]*wz[p];
    }
    float inv = 1.f / den;
    float ox = 0.f, oy = 0.f;
    #pragma unroll
    for (int p = 0; p < NSPLIT_; p++){
        float2 o = *(const float2*)&g_opart[idx[p]*48 + c];
        ox += o.x*wz[p]; oy += o.y*wz[p];
    }
    long long gi = (long long)row*768 + h*48 + c;
    float2 gt = __bfloat1622float2(*(const __nv_bfloat162*)&gateg[gi]);
    *(unsigned*)&og[gi] = f2bf2(ox * inv * gt.x, oy * inv * gt.y);
}

// ---------------- fused pair LN + pl GEMM (bf16 weights, bf16 out) ----------------
__global__ void pwcvt_k(const float* __restrict__ pw){
    int i = blockIdx.x * 256 + threadIdx.x;
    if (i < 8192){
        float2 v = *(const float2*)&pw[i*2];
        *(unsigned*)&g_pwh[i*2] = f2bf2(v.x, v.y);
    }
}

__global__ void pair_k(const float* __restrict__ pc, const float* __restrict__ scale)
{
    __shared__ __align__(16) __nv_bfloat16 spch[64*136];
    __shared__ __align__(16) __nv_bfloat16 spwh[128*72];
    int nsb = blockIdx.x;
    int t = threadIdx.x, lane = t & 31, w = t >> 5;
    long long row0 = (long long)blockIdx.y * 64;
    int arow = ((lane >> 3) & 1) * 8 + (lane & 7);
    int acol = (lane >> 4) << 3;

    for (int i = t; i < 1024; i += 256){
        int kr = i >> 3, n8 = (i & 7) << 3;
        *(uint4*)&spwh[kr*72 + n8] = *(const uint4*)&g_pwh[nsb*8192 + kr*64 + n8];
    }
    float4 sc4 = *(const float4*)&scale[lane*4];
    for (int rr = 0; rr < 8; rr++){
        int r = w*8 + rr;
        float4 xv = *(const float4*)&pc[(row0 + r)*128 + lane*4];
        float s = xv.x + xv.y + xv.z + xv.w;
        #pragma unroll
        for (int o = 16; o; o >>= 1) s += __shfl_xor_sync(0xffffffffu, s, o);
        float m = s * (1.f/128.f);
        float d0 = xv.x - m, d1 = xv.y - m, d2 = xv.z - m, d3 = xv.w - m;
        float vq = d0*d0 + d1*d1 + d2*d2 + d3*d3;
        #pragma unroll
        for (int o = 16; o; o >>= 1) vq += __shfl_xor_sync(0xffffffffu, vq, o);
        float rstd = rsqrtf(vq * (1.f/128.f) + 1e-5f);
        uint2 u;
        u.x = f2bf2(d0*rstd*sc4.x, d1*rstd*sc4.y);
        u.y = f2bf2(d2*rstd*sc4.z, d3*rstd*sc4.w);
        *(uint2*)&spch[r*136 + lane*4] = u;
    }
    __syncthreads();

    int wm = w & 3, wn = w >> 2;
    float acc[4][4];
    #pragma unroll
    for (int i = 0; i < 4; i++)
        #pragma unroll
        for (int q = 0; q < 4; q++) acc[i][q] = 0.f;

    unsigned aB = s2u(spch), bB = s2u(spwh);
    #pragma unroll
    for (int k16 = 0; k16 < 128; k16 += 16){
        unsigned af[4], bf4[2][4];
        ldsm4(af, aB + ((wm*16 + arow)*136 + k16 + acol)*2);
        #pragma unroll
        for (int p = 0; p < 2; p++)
            ldsm4t(bf4[p], bB + ((k16 + (lane & 15))*72 + wn*32 + p*16 + ((lane >> 4) << 3))*2);
        #pragma unroll
        for (int nt = 0; nt < 4; nt++)
            mma_bf16(acc[nt], af, bf4[nt >> 1] + (nt & 1)*2);
    }
    __syncthreads();

    __nv_bfloat16* sbout = spch;
    int r = wm*16 + (lane >> 2);
    #pragma unroll
    for (int nt = 0; nt < 4; nt++){
        int c = wn*32 + nt*8 + 2*(lane & 3);
        sbout[(c  )*72 + r    ] = __float2bfloat16(acc[nt][0]);
        sbout[(c+1)*72 + r    ] = __float2bfloat16(acc[nt][1]);
        sbout[(c  )*72 + r + 8] = __float2bfloat16(acc[nt][2]);
        sbout[(c+1)*72 + r + 8] = __float2bfloat16(acc[nt][3]);
    }
    __syncthreads();
    for (int i = t; i < 512; i += 256){
        int col = i >> 3, m = (i & 7) * 8;
        *(uint4*)&g_pl[((long long)(nsb*64 + col))*NNSQ_ + row0 + m] =
            *(const uint4*)&sbout[col*72 + m];
    }
}

// ---------------- small kernels ----------------
__global__ void bias_k(const float* __restrict__ mask){
    int i = blockIdx.x * 256 + threadIdx.x;
    if (i < NN_) g_bias[i] = 1e9f * (mask[i] - 1.f);
}

__global__ void ln384_k(const float* __restrict__ in){
    int r = blockIdx.x, t = threadIdx.x;
    __shared__ float red[32];
    const float* p = in + (long long)r * CS_;
    float v0 = p[t], v1 = p[t+128], v2 = p[t+256];
    float s = blockReduce(v0+v1+v2, red, false);
    float m = s * (1.f/384.f);
    float d0 = v0-m, d1 = v1-m, d2 = v2-m;
    float q = blockReduce(d0*d0+d1*d1+d2*d2, red, false);
    float rstd = rsqrtf(q * (1.f/384.f) + 1e-5f);
    float* o = g_lnsc + (long long)r * CS_;
    o[t] = d0*rstd; o[t+128] = d1*rstd; o[t+256] = d2*rstd;
}

__global__ void cn_k(const float* __restrict__ aln, const float* __restrict__ fln){
    int i = blockIdx.x * 256 + threadIdx.x;
    if (i >= LL_*NN_*CS_) return;
    int l = i / (NN_*CS_);
    int rem = i % (NN_*CS_);
    int c = rem % CS_;
    float b = g_lnsc[rem];
    g_cnA[i] = b * aln[l*CS_ + c];
    g_cnF[i] = b * fln[l*CS_ + c];
}

__global__ void modulate_k(const float* __restrict__ a, const float* __restrict__ sig,
                           const float* __restrict__ add, __nv_bfloat16* __restrict__ xo){
    int r = blockIdx.x, t = threadIdx.x;
    __shared__ float red[32];
    const float* ar = a + (long long)r * 768;
    float v0 = ar[t], v1 = ar[t+256], v2 = ar[t+512];
    float s = blockReduce(v0+v1+v2, red, false);
    float m = s * (1.f/768.f);
    float d0 = v0-m, d1 = v1-m, d2 = v2-m;
    float q = blockReduce(d0*d0+d1*d1+d2*d2, red, false);
    float rstd = rsqrtf(q * (1.f/768.f) + 1e-5f);
    long long o = (long long)r * 768;
    xo[o+t]     = __float2bfloat16(sig[o+t]     * (d0*rstd) + add[o+t]);
    xo[o+t+256] = __float2bfloat16(sig[o+t+256] * (d1*rstd) + add[o+t+256]);
    xo[o+t+512] = __float2bfloat16(sig[o+t+512] * (d2*rstd) + add[o+t+512]);
}

// ---------------- host ----------------
extern "C" void kernel_launch(void* const* d_in, const int* in_sizes, int n_in,
                              void* d_out, int out_size)
{
    const float* act         = (const float*)d_in[0];
    const float* mask        = (const float*)d_in[1];
    const float* single_cond = (const float*)d_in[2];
    const float* pair_cond   = (const float*)d_in[3];
    const float* attn_cln    = (const float*)d_in[4];
    const float* attn_cs_w   = (const float*)d_in[5];
    const float* attn_cs_b   = (const float*)d_in[6];
    const float* attn_cb_w   = (const float*)d_in[7];
    const float* q_w         = (const float*)d_in[8];
    const float* q_b         = (const float*)d_in[9];
    const float* k_w         = (const float*)d_in[10];
    const float* v_w         = (const float*)d_in[11];
    const float* gate_w      = (const float*)d_in[12];
    const float* gate_b      = (const float*)d_in[13];
    const float* out_w       = (const float*)d_in[14];
    const float* attn_azc_w  = (const float*)d_in[15];
    const float* attn_azc_b  = (const float*)d_in[16];
    const float* ffw_cln     = (const float*)d_in[17];
    const float* ffw_cs_w    = (const float*)d_in[18];
    const float* ffw_cs_b    = (const float*)d_in[19];
    const float* ffw_cb_w    = (const float*)d_in[20];
    const float* t1_w        = (const float*)d_in[21];
    const float* t2_w        = (const float*)d_in[22];
    const float* ffw_azc_w   = (const float*)d_in[23];
    const float* ffw_azc_b   = (const float*)d_in[24];
    const float* pair_lns    = (const float*)d_in[25];
    const float* pair_w      = (const float*)d_in[26];
    float* a = (float*)d_out;

    __nv_bfloat16 *pl, *x, *qb, *kb, *vb, *gb, *wab, *ub;
    float *cnA, *cnF, *sigA, *addA, *azcA, *sigF, *addF, *azcF;
    cudaGetSymbolAddress((void**)&pl,   g_pl);
    cudaGetSymbolAddress((void**)&x,    g_x);
    cudaGetSymbolAddress((void**)&qb,   g_q);
    cudaGetSymbolAddress((void**)&kb,   g_k);
    cudaGetSymbolAddress((void**)&vb,   g_v);
    cudaGetSymbolAddress((void**)&gb,   g_gate);
    cudaGetSymbolAddress((void**)&wab,  g_wa);
    cudaGetSymbolAddress((void**)&ub,   g_u);
    cudaGetSymbolAddress((void**)&cnA,  g_cnA);
    cudaGetSymbolAddress((void**)&cnF,  g_cnF);
    cudaGetSymbolAddress((void**)&sigA, g_sigA);
    cudaGetSymbolAddress((void**)&addA, g_addA);
    cudaGetSymbolAddress((void**)&azcA, g_azcA);
    cudaGetSymbolAddress((void**)&sigF, g_sigF);
    cudaGetSymbolAddress((void**)&addF, g_addF);
    cudaGetSymbolAddress((void**)&azcF, g_azcF);

    cudaMemcpyAsync(a, act, (size_t)NC_ * sizeof(float), cudaMemcpyDeviceToDevice);

    bias_k<<<3, 256>>>(mask);
    ln384_k<<<NN_, 128>>>(single_cond);
    cn_k<<<(LL_*NN_*CS_ + 255)/256, 256>>>(attn_cln, ffw_cln);
    pwcvt_k<<<32, 256>>>(pair_w);

    pair_k<<<dim3(2, 9216), 256>>>(pair_cond, pair_lns);

    pre6_tc<<<dim3(12, 12, 48), 256>>>(cnA, cnF, single_cond,
        attn_cs_w, attn_cb_w, attn_azc_w, ffw_cs_w, ffw_cb_w, ffw_azc_w,
        sigA, addA, azcA, sigF, addF, azcF,
        attn_cs_b, attn_azc_b, ffw_cs_b, ffw_azc_b);

    cudaFuncSetAttribute(flash_k, cudaFuncAttributeMaxDynamicSharedMemorySize, 58368);

    for (int l = 0; l < 8; l++){
        long long oNC = (long long)l * NC_;
        modulate_k<<<768, 256>>>(a, sigA + oNC, addA + oNC, x);
        qkvg_tc<<<dim3(12, 12, 4), 256>>>(x,
            q_w + oNC, k_w + oNC, v_w + oNC, gate_w + oNC,
            qb, kb, vb, gb, q_b + l*768, gate_b + l*768);
        flash_k<<<dim3(16, 12, NSPLIT_), 256, 58368>>>(qb, kb, vb,
            pl + (long long)l * HH_ * NNSQ_);
        comb_k<<<768, 384>>>(gb, wab);
        gemm_tc<32,1,0,0><<<dim3(12, 24, 1), 256>>>(768, wab, 768, 0, out_w + oNC, 768, 0,
            a, 768, 0, 4, azcA + oNC, 0);
        modulate_k<<<768, 256>>>(a, sigF + oNC, addF + oNC, x);
        gemm_tc<64,1,1,0><<<dim3(48, 12, 1), 256>>>(768, x, 768, 0, t1_w + (long long)l*768*3072, 3072, 0,
            ub, 3072, 0, 0, (const float*)0, 0);
        // t2 with GLU fused into A staging: A[m][k] = swish(u[m][k]) * u[m][k+1536]
        gemm_tc<32,1,0,1><<<dim3(12, 24, 1), 256>>>(1536, ub, 3072, 0, t2_w + (long long)l*1536*768, 768, 0,
            a, 768, 0, 4, azcF + oNC, 0);
    }
    (void)in_sizes; (void)n_in; (void)out_size;
}

// round 17
// speedup vs baseline: 1.1087x; 1.1087x over previous
#include <cuda_runtime.h>
#include <cuda_bf16.h>
#include <math.h>

#define NN_ 768
#define CC_ 768
#define CS_ 384
#define HH_ 16
#define FF_ 1536
#define LL_ 8
#define NC_ (NN_*CC_)
#define NNSQ_ 589824LL
#define NSPLIT_ 2

// ---------------- scratch ----------------
__device__ static __nv_bfloat16 g_pl[LL_*HH_*NN_*NN_];
__device__ static __nv_bfloat16 g_pwh[2*8192];
__device__ static __nv_bfloat16 g_x[NC_];
__device__ static __nv_bfloat16 g_q[NC_], g_k[NC_], g_v[NC_], g_gate[NC_], g_wa[NC_];
__device__ static __nv_bfloat16 g_u[NN_*2*FF_];
__device__ static __nv_bfloat16 g_c[NN_*FF_];
__device__ static float g_opart[NSPLIT_*HH_*NN_*48];
__device__ static float g_ml[NSPLIT_*HH_*NN_*2];
__device__ static float g_lnsc[NN_*CS_];
__device__ static float g_cnA[LL_*NN_*CS_], g_cnF[LL_*NN_*CS_];
__device__ static float g_sigA[LL_*NC_], g_addA[LL_*NC_], g_azcA[LL_*NC_];
__device__ static float g_sigF[LL_*NC_], g_addF[LL_*NC_], g_azcF[LL_*NC_];
__device__ static float g_bias[NN_];

// ---------------- bf16 mma helpers ----------------
__device__ __forceinline__ unsigned f2bf2(float lo, float hi){
    unsigned r; asm("cvt.rn.bf16x2.f32 %0, %1, %2;" : "=r"(r) : "f"(hi), "f"(lo)); return r;
}
__device__ __forceinline__ unsigned s2u(const void* p){
    return (unsigned)__cvta_generic_to_shared(p);
}
__device__ __forceinline__ void ldsm4(unsigned* r, unsigned a){
    asm volatile("ldmatrix.sync.aligned.m8n8.x4.shared.b16 {%0,%1,%2,%3}, [%4];"
        : "=r"(r[0]),"=r"(r[1]),"=r"(r[2]),"=r"(r[3]) : "r"(a));
}
__device__ __forceinline__ void ldsm2(unsigned* r, unsigned a){
    asm volatile("ldmatrix.sync.aligned.m8n8.x2.shared.b16 {%0,%1}, [%2];"
        : "=r"(r[0]),"=r"(r[1]) : "r"(a));
}
__device__ __forceinline__ void ldsm2t(unsigned* r, unsigned a){
    asm volatile("ldmatrix.sync.aligned.m8n8.x2.trans.shared.b16 {%0,%1}, [%2];"
        : "=r"(r[0]),"=r"(r[1]) : "r"(a));
}
__device__ __forceinline__ void ldsm4t(unsigned* r, unsigned a){
    asm volatile("ldmatrix.sync.aligned.m8n8.x4.trans.shared.b16 {%0,%1,%2,%3}, [%4];"
        : "=r"(r[0]),"=r"(r[1]),"=r"(r[2]),"=r"(r[3]) : "r"(a));
}
__device__ __forceinline__ void mma_bf16(float* c, const unsigned* a, const unsigned* b){
    asm volatile("mma.sync.aligned.m16n8k16.row.col.f32.bf16.bf16.f32 "
        "{%0,%1,%2,%3}, {%4,%5,%6,%7}, {%8,%9}, {%0,%1,%2,%3};"
        : "+f"(c[0]),"+f"(c[1]),"+f"(c[2]),"+f"(c[3])
        : "r"(a[0]),"r"(a[1]),"r"(a[2]),"r"(a[3]),"r"(b[0]),"r"(b[1]));
}

// ---------------- reductions ----------------
__device__ __forceinline__ float blockReduce(float v, float* red, bool ismax){
    __syncthreads();
    int lane = threadIdx.x & 31, w = threadIdx.x >> 5, nw = blockDim.x >> 5;
    #pragma unroll
    for (int o = 16; o; o >>= 1){
        float u = __shfl_xor_sync(0xffffffffu, v, o);
        v = ismax ? fmaxf(v, u) : v + u;
    }
    if (lane == 0) red[w] = v;
    __syncthreads();
    if (w == 0){
        v = (lane < nw) ? red[lane] : (ismax ? -1e30f : 0.f);
        #pragma unroll
        for (int o = 16; o; o >>= 1){
            float u = __shfl_xor_sync(0xffffffffu, v, o);
            v = ismax ? fmaxf(v, u) : v + u;
        }
        if (lane == 0) red[0] = v;
    }
    __syncthreads();
    return red[0];
}

// ---------------- epilogue value transform ----------------
__device__ __forceinline__ float epv(int mode, const float* P1, int n, float r){
    if (mode == 1) return r + P1[n];
    if (mode == 2) return 1.f / (1.f + __expf(-(r + P1[n])));
    return r;
}

// ---------------- bf16 GEMM body: MROWSx64 tile, BK=32, 256 thr, double-buffered ----------------
template<int MROWS, int ABF, int CBF>
__device__ __forceinline__ void gemm_body(int K,
    const void* __restrict__ Av, int lda,
    const float* __restrict__ B, int ldb,
    void* __restrict__ Cv, int ldc,
    int mode, const float* __restrict__ P1,
    __nv_bfloat16* Asb, __nv_bfloat16* Bsb)
{
    const float* Af = (const float*)Av;
    const __nv_bfloat16* Ah = (const __nv_bfloat16*)Av;
    constexpr int MH  = MROWS / 2;
    constexpr int NMT = MH / 16;
    constexpr int NAC = MROWS / 32;

    int bm = blockIdx.y * MROWS, bn = blockIdx.x << 6;
    int t = threadIdx.x, lane = t & 31, w = t >> 5;
    int wm = w & 1, wn = w >> 1;
    int a_r = t >> 3, a_c = (t & 7) << 2;
    int a8_r = t >> 2, a8_c = (t & 3) << 3;
    int b_r = t >> 4, b_c = (t & 15) << 2;
    int arow = ((lane >> 3) & 1) * 8 + (lane & 7);
    int acol = (lane >> 4) << 3;
    bool a8on = (a8_r < MROWS);

    float acc[NMT][2][4];
    #pragma unroll
    for (int i = 0; i < NMT; i++)
        #pragma unroll
        for (int j = 0; j < 2; j++)
            #pragma unroll
            for (int q = 0; q < 4; q++) acc[i][j][q] = 0.f;

    float4 raf[NAC]; uint4 rah;
    if (ABF){
        if (a8on) rah = *(const uint4*)&Ah[(long long)(bm + a8_r)*lda + a8_c];
    } else {
        #pragma unroll
        for (int i = 0; i < NAC; i++)
            raf[i] = *(const float4*)&Af[(long long)(bm + a_r + 32*i)*lda + a_c];
    }
    float4 rb0 = *(const float4*)&B[(long long)b_r*ldb + bn + b_c];
    float4 rb1 = *(const float4*)&B[(long long)(b_r + 16)*ldb + bn + b_c];

    int nk = K >> 5;
    for (int it = 0;;){
        __nv_bfloat16* As = Asb + (it & 1) * (MROWS*40);
        __nv_bfloat16* Bs = Bsb + (it & 1) * (32*72);
        uint2 u;
        if (ABF){
            if (a8on) *(uint4*)&As[a8_r*40 + a8_c] = rah;
        } else {
            #pragma unroll
            for (int i = 0; i < NAC; i++){
                u.x = f2bf2(raf[i].x, raf[i].y); u.y = f2bf2(raf[i].z, raf[i].w);
                *(uint2*)&As[(a_r + 32*i)*40 + a_c] = u;
            }
        }
        u.x = f2bf2(rb0.x, rb0.y); u.y = f2bf2(rb0.z, rb0.w);
        *(uint2*)&Bs[b_r*72 + b_c] = u;
        u.x = f2bf2(rb1.x, rb1.y); u.y = f2bf2(rb1.z, rb1.w);
        *(uint2*)&Bs[(b_r + 16)*72 + b_c] = u;
        __syncthreads();

        int itn = it + 1;
        if (itn < nk){
            int k1 = itn << 5;
            if (ABF){
                if (a8on) rah = *(const uint4*)&Ah[(long long)(bm + a8_r)*lda + k1 + a8_c];
            } else {
                #pragma unroll
                for (int i = 0; i < NAC; i++)
                    raf[i] = *(const float4*)&Af[(long long)(bm + a_r + 32*i)*lda + k1 + a_c];
            }
            rb0 = *(const float4*)&B[(long long)(k1 + b_r)*ldb + bn + b_c];
            rb1 = *(const float4*)&B[(long long)(k1 + b_r + 16)*ldb + bn + b_c];
        }

        unsigned aB = s2u(As), bB = s2u(Bs);
        #pragma unroll
        for (int k16 = 0; k16 < 32; k16 += 16){
            unsigned af[NMT][4], bf[2][2];
            #pragma unroll
            for (int mt = 0; mt < NMT; mt++)
                ldsm4(af[mt], aB + ((wm*MH + mt*16 + arow)*40 + k16 + acol)*2);
            #pragma unroll
            for (int nt = 0; nt < 2; nt++)
                ldsm2t(bf[nt], bB + ((k16 + (lane & 15))*72 + wn*16 + nt*8)*2);
            #pragma unroll
            for (int mt = 0; mt < NMT; mt++)
                #pragma unroll
                for (int nt = 0; nt < 2; nt++)
                    mma_bf16(acc[mt][nt], af[mt], bf[nt]);
        }
        it = itn;
        if (it >= nk) break;
    }

    #pragma unroll
    for (int mt = 0; mt < NMT; mt++){
        int r0 = bm + wm*MH + mt*16 + (lane >> 2);
        #pragma unroll
        for (int nt = 0; nt < 2; nt++){
            int c0 = bn + wn*16 + nt*8 + 2*(lane & 3);
            float* ac = acc[mt][nt];
            if (CBF){
                __nv_bfloat16* Ch = (__nv_bfloat16*)Cv;
                *(unsigned*)&Ch[(long long)r0*ldc + c0] =
                    f2bf2(epv(mode, P1, c0, ac[0]), epv(mode, P1, c0+1, ac[1]));
                *(unsigned*)&Ch[(long long)(r0+8)*ldc + c0] =
                    f2bf2(epv(mode, P1, c0, ac[2]), epv(mode, P1, c0+1, ac[3]));
            } else {
                float* Cf = (float*)Cv;
                long long ci0 = (long long)r0*ldc + c0;
                long long ci1 = (long long)(r0+8)*ldc + c0;
                if (mode == 4){
                    float2 c0v = *(float2*)&Cf[ci0];
                    float2 p0v = *(const float2*)&P1[ci0];
                    float2 c1v = *(float2*)&Cf[ci1];
                    float2 p1v = *(const float2*)&P1[ci1];
                    c0v.x += p0v.x * ac[0]; c0v.y += p0v.y * ac[1];
                    c1v.x += p1v.x * ac[2]; c1v.y += p1v.y * ac[3];
                    *(float2*)&Cf[ci0] = c0v;
                    *(float2*)&Cf[ci1] = c1v;
                } else {
                    Cf[ci0]   = epv(mode, P1, c0,   ac[0]);
                    Cf[ci0+1] = epv(mode, P1, c0+1, ac[1]);
                    Cf[ci1]   = epv(mode, P1, c0,   ac[2]);
                    Cf[ci1+1] = epv(mode, P1, c0+1, ac[3]);
                }
            }
        }
    }
}

template<int MROWS, int ABF, int CBF>
__global__ void gemm_tc(int K,
    const void* __restrict__ A, int lda, long long sA,
    const float* __restrict__ B, int ldb, long long sB,
    void* __restrict__ C, int ldc, long long sC,
    int mode, const float* __restrict__ P1, long long sP1)
{
    __shared__ __align__(16) __nv_bfloat16 As[2*MROWS*40];
    __shared__ __align__(16) __nv_bfloat16 Bs[2*32*72];
    int bz = blockIdx.z;
    const void* Ab = ABF ? (const void*)((const __nv_bfloat16*)A + (long long)bz*sA)
                         : (const void*)((const float*)A + (long long)bz*sA);
    void* Cb = CBF ? (void*)((__nv_bfloat16*)C + (long long)bz*sC)
                   : (void*)((float*)C + (long long)bz*sC);
    gemm_body<MROWS,ABF,CBF>(K, Ab, lda, B + (long long)bz*sB, ldb, Cb, ldc, mode,
                P1 ? P1 + (long long)bz*sP1 : P1, As, Bs);
}

// all 6 conditioning precompute GEMMs in one launch (grid.z = 48; z/8 selects config)
__global__ void pre6_tc(const float* __restrict__ cnA, const float* __restrict__ cnF,
    const float* __restrict__ sc,
    const float* __restrict__ csA, const float* __restrict__ cbA, const float* __restrict__ azA,
    const float* __restrict__ csF, const float* __restrict__ cbF, const float* __restrict__ azF,
    float* __restrict__ sigA, float* __restrict__ addA, float* __restrict__ azcA,
    float* __restrict__ sigF, float* __restrict__ addF, float* __restrict__ azcF,
    const float* __restrict__ csbA, const float* __restrict__ azbA,
    const float* __restrict__ csbF, const float* __restrict__ azbF)
{
    __shared__ __align__(16) __nv_bfloat16 As[2*64*40];
    __shared__ __align__(16) __nv_bfloat16 Bs[2*32*72];
    int g = blockIdx.z >> 3, bz = blockIdx.z & 7;
    const float* A; const float* B; float* C; int mode; const float* P1; long long sA;
    switch (g){
        case 0: A = cnA; sA = (long long)NN_*CS_; B = csA; C = sigA; mode = 2; P1 = csbA; break;
        case 1: A = cnA; sA = (long long)NN_*CS_; B = cbA; C = addA; mode = 0; P1 = 0;    break;
        case 2: A = sc;  sA = 0;                  B = azA; C = azcA; mode = 2; P1 = azbA; break;
        case 3: A = cnF; sA = (long long)NN_*CS_; B = csF; C = sigF; mode = 2; P1 = csbF; break;
        case 4: A = cnF; sA = (long long)NN_*CS_; B = cbF; C = addF; mode = 0; P1 = 0;    break;
        default:A = sc;  sA = 0;                  B = azF; C = azcF; mode = 2; P1 = azbF; break;
    }
    A += (long long)bz * sA;
    B += (long long)bz * CS_ * CC_;
    C += (long long)bz * NC_;
    if (P1) P1 += bz * 768;
    gemm_body<64,0,0>(384, A, 384, B, 768, (void*)C, 768, mode, P1, As, Bs);
}

// fused QKV+gate: A bf16, outputs bf16 (64-row tiles)
__global__ void qkvg_tc(const __nv_bfloat16* __restrict__ A,
    const float* __restrict__ Bq, const float* __restrict__ Bk,
    const float* __restrict__ Bv, const float* __restrict__ Bg,
    __nv_bfloat16* __restrict__ Cq, __nv_bfloat16* __restrict__ Ck,
    __nv_bfloat16* __restrict__ Cv, __nv_bfloat16* __restrict__ Cg,
    const float* __restrict__ biasq, const float* __restrict__ biasg)
{
    __shared__ __align__(16) __nv_bfloat16 As[2*64*40];
    __shared__ __align__(16) __nv_bfloat16 Bs[2*32*72];
    int z = blockIdx.z;
    const float* B = (z==0) ? Bq : (z==1) ? Bk : (z==2) ? Bv : Bg;
    __nv_bfloat16* C = (z==0) ? Cq : (z==1) ? Ck : (z==2) ? Cv : Cg;
    int mode       = (z==0) ? 1 : (z==3) ? 2 : 0;
    const float* P1= (z==0) ? biasq : (z==3) ? biasg : (const float*)0;
    gemm_body<64,1,1>(768, A, 768, B, 768, (void*)C, 768, mode, P1, As, Bs);
}

// ---------------- flash, split-kv: grid (16,12,NSPLIT_); bias pre-folded into pl ----------------
__global__ void flash_k(const __nv_bfloat16* __restrict__ qg, const __nv_bfloat16* __restrict__ kg,
                        const __nv_bfloat16* __restrict__ vg,
                        const __nv_bfloat16* __restrict__ plg)
{
    extern __shared__ __align__(16) char fsm[];
    __nv_bfloat16* Qs   = (__nv_bfloat16*)fsm;   // 64x56
    __nv_bfloat16* Ks   = Qs + 64*56;            // 2 x 64x56
    __nv_bfloat16* Vs   = Ks + 2*64*56;          // 2 x 64x56
    __nv_bfloat16* plsh = Vs + 2*64*56;          // 2 x 64x72
    float* redm   = (float*)(plsh + 2*64*72);    // 2x64
    float* reds   = redm + 128;                  // 2x64
    float* Of     = (float*)plsh;                // reused after loop (64x52)

    const float scale = 0.14433756729740643f;
    int h = blockIdx.x, q0 = blockIdx.y * 64;
    int z = blockIdx.z;
    int ktlo = z*(12/NSPLIT_), kthi = ktlo + (12/NSPLIT_);
    int t = threadIdx.x, lane = t & 31, w = t >> 5;
    int wm = w & 3, wn = w >> 2;
    int r0l = wm*16 + (lane >> 2), r1l = r0l + 8;
    int arow = ((lane >> 3) & 1) * 8 + (lane & 7);
    int acol = (lane >> 4) << 3;

    int kv_r0 = t / 6,        kv_c0 = (t % 6) * 8;
    int kv_r1 = (t + 256)/6,  kv_c1 = ((t + 256) % 6) * 8;
    bool kv2 = (t < 128);
    int pl_r0 = t >> 3,          pl_c0 = (t & 7) * 8;
    int pl_r1 = (t + 256) >> 3,  pl_c1 = ((t + 256) & 7) * 8;

    // stage Q + first tile of this part (into local buffer 0)
    for (int i = t; i < 384; i += 256){
        int r = i / 6, c8 = (i % 6) * 8;
        *(uint4*)&Qs[r*56 + c8] = *(const uint4*)&qg[(long long)(q0 + r)*768 + h*48 + c8];
    }
    {
        int kb0 = ktlo * 64;
        *(uint4*)&Ks[kv_r0*56 + kv_c0] = *(const uint4*)&kg[(long long)(kb0 + kv_r0)*768 + h*48 + kv_c0];
        *(uint4*)&Vs[kv_r0*56 + kv_c0] = *(const uint4*)&vg[(long long)(kb0 + kv_r0)*768 + h*48 + kv_c0];
        if (kv2){
            *(uint4*)&Ks[kv_r1*56 + kv_c1] = *(const uint4*)&kg[(long long)(kb0 + kv_r1)*768 + h*48 + kv_c1];
            *(uint4*)&Vs[kv_r1*56 + kv_c1] = *(const uint4*)&vg[(long long)(kb0 + kv_r1)*768 + h*48 + kv_c1];
        }
        *(uint4*)&plsh[pl_r0*72 + pl_c0] = *(const uint4*)&plg[((long long)h*768 + q0 + pl_r0)*768 + kb0 + pl_c0];
        *(uint4*)&plsh[pl_r1*72 + pl_c1] = *(const uint4*)&plg[((long long)h*768 + q0 + pl_r1)*768 + kb0 + pl_c1];
    }
    __syncthreads();
    unsigned qB = s2u(Qs);
    unsigned aq[3][4];
    #pragma unroll
    for (int kk = 0; kk < 3; kk++)
        ldsm4(aq[kk], qB + ((wm*16 + arow)*56 + kk*16 + acol)*2);

    float m0o = -1e30f, m1o = -1e30f, l0 = 0.f, l1 = 0.f;
    float acc[6][4];
    #pragma unroll
    for (int i = 0; i < 6; i++)
        #pragma unroll
        for (int q = 0; q < 4; q++) acc[i][q] = 0.f;

    for (int kt = ktlo; kt < kthi; kt++){
        int buf = (kt - ktlo) & 1;
        __nv_bfloat16* Kb = Ks + buf*(64*56);
        __nv_bfloat16* Vb = Vs + buf*(64*56);
        __nv_bfloat16* Pb = plsh + buf*(64*72);
        unsigned kB = s2u(Kb), vB = s2u(Vb);
        int k0 = kt * 64;

        uint4 pk0, pk1, pv0, pv1, pp0, pp1;
        if (kt + 1 < kthi){
            int k1 = k0 + 64;
            pk0 = *(const uint4*)&kg[(long long)(k1 + kv_r0)*768 + h*48 + kv_c0];
            pv0 = *(const uint4*)&vg[(long long)(k1 + kv_r0)*768 + h*48 + kv_c0];
            if (kv2){
                pk1 = *(const uint4*)&kg[(long long)(k1 + kv_r1)*768 + h*48 + kv_c1];
                pv1 = *(const uint4*)&vg[(long long)(k1 + kv_r1)*768 + h*48 + kv_c1];
            }
            pp0 = *(const uint4*)&plg[((long long)h*768 + q0 + pl_r0)*768 + k1 + pl_c0];
            pp1 = *(const uint4*)&plg[((long long)h*768 + q0 + pl_r1)*768 + k1 + pl_c1];
        }

        float s[4][4];
        #pragma unroll
        for (int i = 0; i < 4; i++)
            #pragma unroll
            for (int q = 0; q < 4; q++) s[i][q] = 0.f;
        #pragma unroll
        for (int kk = 0; kk < 3; kk++){
            #pragma unroll
            for (int nt = 0; nt < 4; nt++){
                unsigned bk[2];
                ldsm2(bk, kB + ((wn*32 + nt*8 + (lane & 7))*56 + kk*16 + (lane & 8))*2);
                mma_bf16(s[nt], aq[kk], bk);
            }
        }
        float rm0 = -1e30f, rm1 = -1e30f;
        #pragma unroll
        for (int nt = 0; nt < 4; nt++){
            int c = wn*32 + nt*8 + 2*(lane & 3);
            float2 p0 = __bfloat1622float2(*(const __nv_bfloat162*)&Pb[r0l*72 + c]);
            float2 p1 = __bfloat1622float2(*(const __nv_bfloat162*)&Pb[r1l*72 + c]);
            s[nt][0] = fmaf(s[nt][0], scale, p0.x);
            s[nt][1] = fmaf(s[nt][1], scale, p0.y);
            s[nt][2] = fmaf(s[nt][2], scale, p1.x);
            s[nt][3] = fmaf(s[nt][3], scale, p1.y);
            rm0 = fmaxf(rm0, fmaxf(s[nt][0], s[nt][1]));
            rm1 = fmaxf(rm1, fmaxf(s[nt][2], s[nt][3]));
        }
        rm0 = fmaxf(rm0, __shfl_xor_sync(0xffffffffu, rm0, 1));
        rm0 = fmaxf(rm0, __shfl_xor_sync(0xffffffffu, rm0, 2));
        rm1 = fmaxf(rm1, __shfl_xor_sync(0xffffffffu, rm1, 1));
        rm1 = fmaxf(rm1, __shfl_xor_sync(0xffffffffu, rm1, 2));
        if ((lane & 3) == 0){ redm[wn*64 + r0l] = rm0; redm[wn*64 + r1l] = rm1; }
        __syncthreads();
        float m0 = fmaxf(m0o, fmaxf(redm[r0l], redm[64 + r0l]));
        float m1 = fmaxf(m1o, fmaxf(redm[r1l], redm[64 + r1l]));
        float sc0 = __expf(m0o - m0), sc1 = __expf(m1o - m1);
        m0o = m0; m1o = m1;
        float rs0 = 0.f, rs1 = 0.f;
        #pragma unroll
        for (int nt = 0; nt < 4; nt++){
            s[nt][0] = __expf(s[nt][0] - m0);
            s[nt][1] = __expf(s[nt][1] - m0);
            s[nt][2] = __expf(s[nt][2] - m1);
            s[nt][3] = __expf(s[nt][3] - m1);
            rs0 += s[nt][0] + s[nt][1];
            rs1 += s[nt][2] + s[nt][3];
        }
        rs0 += __shfl_xor_sync(0xffffffffu, rs0, 1);
        rs0 += __shfl_xor_sync(0xffffffffu, rs0, 2);
        rs1 += __shfl_xor_sync(0xffffffffu, rs1, 1);
        rs1 += __shfl_xor_sync(0xffffffffu, rs1, 2);
        if ((lane & 3) == 0){ reds[wn*64 + r0l] = rs0; reds[wn*64 + r1l] = rs1; }
        #pragma unroll
        for (int nt = 0; nt < 6; nt++){
            acc[nt][0] *= sc0; acc[nt][1] *= sc0;
            acc[nt][2] *= sc1; acc[nt][3] *= sc1;
        }
        __syncthreads();
        l0 = l0 * sc0 + reds[r0l] + reds[64 + r0l];
        l1 = l1 * sc1 + reds[r1l] + reds[64 + r1l];
        #pragma unroll
        for (int c16 = 0; c16 < 2; c16++){
            unsigned ap[4];
            ap[0] = f2bf2(s[2*c16  ][0], s[2*c16  ][1]);
            ap[1] = f2bf2(s[2*c16  ][2], s[2*c16  ][3]);
            ap[2] = f2bf2(s[2*c16+1][0], s[2*c16+1][1]);
            ap[3] = f2bf2(s[2*c16+1][2], s[2*c16+1][3]);
            #pragma unroll
            for (int nt = 0; nt < 6; nt++){
                unsigned bv[2];
                ldsm2t(bv, vB + ((wn*32 + c16*16 + (lane & 15))*56 + nt*8)*2);
                mma_bf16(acc[nt], ap, bv);
            }
        }
        if (kt + 1 < kthi){
            __nv_bfloat16* Kn = Ks + (buf^1)*(64*56);
            __nv_bfloat16* Vn = Vs + (buf^1)*(64*56);
            __nv_bfloat16* Pn = plsh + (buf^1)*(64*72);
            *(uint4*)&Kn[kv_r0*56 + kv_c0] = pk0;
            *(uint4*)&Vn[kv_r0*56 + kv_c0] = pv0;
            if (kv2){
                *(uint4*)&Kn[kv_r1*56 + kv_c1] = pk1;
                *(uint4*)&Vn[kv_r1*56 + kv_c1] = pv1;
            }
            *(uint4*)&Pn[pl_r0*72 + pl_c0] = pp0;
            *(uint4*)&Pn[pl_r1*72 + pl_c1] = pp1;
            __syncthreads();
        }
    }

    // merge the two kv-quarter (wn) partial O's; write unnormalized partial + (m,l)
    __syncthreads();
    if (wn == 1){
        #pragma unroll
        for (int nt = 0; nt < 6; nt++){
            int c = nt*8 + 2*(lane & 3);
            *(float2*)&Of[r0l*52 + c] = make_float2(acc[nt][0], acc[nt][1]);
            *(float2*)&Of[r1l*52 + c] = make_float2(acc[nt][2], acc[nt][3]);
        }
    }
    __syncthreads();
    if (wn == 0){
        long long base = ((long long)(z*HH_ + h)*NN_ + q0);
        #pragma unroll
        for (int nt = 0; nt < 6; nt++){
            int c = nt*8 + 2*(lane & 3);
            float2 o0 = *(float2*)&Of[r0l*52 + c];
            float2 o1 = *(float2*)&Of[r1l*52 + c];
            *(float2*)&g_opart[(base + r0l)*48 + c] =
                make_float2(acc[nt][0] + o0.x, acc[nt][1] + o0.y);
            *(float2*)&g_opart[(base + r1l)*48 + c] =
                make_float2(acc[nt][2] + o1.x, acc[nt][3] + o1.y);
        }
        if ((lane & 3) == 0){
            g_ml[(base + r0l)*2    ] = m0o;
            g_ml[(base + r0l)*2 + 1] = l0;
            g_ml[(base + r1l)*2    ] = m1o;
            g_ml[(base + r1l)*2 + 1] = l1;
        }
    }
}

// combine the NSPLIT_ kv parts: softmax merge + gate, bf16 out
__global__ void comb_k(const __nv_bfloat16* __restrict__ gateg, __nv_bfloat16* __restrict__ og){
    int row = blockIdx.x, tid = threadIdx.x;      // 384 threads
    int h = tid / 24, c = (tid % 24) * 2;
    long long idx[NSPLIT_];
    float mz[NSPLIT_], lz[NSPLIT_];
    float m = -1e30f;
    #pragma unroll
    for (int p = 0; p < NSPLIT_; p++){
        idx[p] = (long long)(p*HH_ + h)*NN_ + row;
        mz[p] = g_ml[idx[p]*2];
        lz[p] = g_ml[idx[p]*2 + 1];
        m = fmaxf(m, mz[p]);
    }
    float den = 0.f;
    float wz[NSPLIT_];
    #pragma unroll
    for (int p = 0; p < NSPLIT_; p++){
        wz[p] = __expf(mz[p] - m);
        den += lz[p]*wz[p];
    }
    float inv = 1.f / den;
    float ox = 0.f, oy = 0.f;
    #pragma unroll
    for (int p = 0; p < NSPLIT_; p++){
        float2 o = *(const float2*)&g_opart[idx[p]*48 + c];
        ox += o.x*wz[p]; oy += o.y*wz[p];
    }
    long long gi = (long long)row*768 + h*48 + c;
    float2 gt = __bfloat1622float2(*(const __nv_bfloat162*)&gateg[gi]);
    *(unsigned*)&og[gi] = f2bf2(ox * inv * gt.x, oy * inv * gt.y);
}

// ---------------- fused pair LN + pl GEMM (bf16 weights, bias folded, bf16 out) ----------------
__global__ void pwcvt_k(const float* __restrict__ pw){
    int i = blockIdx.x * 256 + threadIdx.x;
    if (i < 8192){
        float2 v = *(const float2*)&pw[i*2];
        *(unsigned*)&g_pwh[i*2] = f2bf2(v.x, v.y);
    }
}

__global__ void pair_k(const float* __restrict__ pc, const float* __restrict__ scale)
{
    __shared__ __align__(16) __nv_bfloat16 spch[64*136];
    __shared__ __align__(16) __nv_bfloat16 spwh[128*72];
    int nsb = blockIdx.x;
    int t = threadIdx.x, lane = t & 31, w = t >> 5;
    long long row0 = (long long)blockIdx.y * 64;
    int arow = ((lane >> 3) & 1) * 8 + (lane & 7);
    int acol = (lane >> 4) << 3;

    for (int i = t; i < 1024; i += 256){
        int kr = i >> 3, n8 = (i & 7) << 3;
        *(uint4*)&spwh[kr*72 + n8] = *(const uint4*)&g_pwh[nsb*8192 + kr*64 + n8];
    }
    float4 sc4 = *(const float4*)&scale[lane*4];
    for (int rr = 0; rr < 8; rr++){
        int r = w*8 + rr;
        float4 xv = *(const float4*)&pc[(row0 + r)*128 + lane*4];
        float s = xv.x + xv.y + xv.z + xv.w;
        #pragma unroll
        for (int o = 16; o; o >>= 1) s += __shfl_xor_sync(0xffffffffu, s, o);
        float m = s * (1.f/128.f);
        float d0 = xv.x - m, d1 = xv.y - m, d2 = xv.z - m, d3 = xv.w - m;
        float vq = d0*d0 + d1*d1 + d2*d2 + d3*d3;
        #pragma unroll
        for (int o = 16; o; o >>= 1) vq += __shfl_xor_sync(0xffffffffu, vq, o);
        float rstd = rsqrtf(vq * (1.f/128.f) + 1e-5f);
        uint2 u;
        u.x = f2bf2(d0*rstd*sc4.x, d1*rstd*sc4.y);
        u.y = f2bf2(d2*rstd*sc4.z, d3*rstd*sc4.w);
        *(uint2*)&spch[r*136 + lane*4] = u;
    }
    __syncthreads();

    int wm = w & 3, wn = w >> 2;
    float acc[4][4];
    #pragma unroll
    for (int i = 0; i < 4; i++)
        #pragma unroll
        for (int q = 0; q < 4; q++) acc[i][q] = 0.f;

    unsigned aB = s2u(spch), bB = s2u(spwh);
    #pragma unroll
    for (int k16 = 0; k16 < 128; k16 += 16){
        unsigned af[4], bf4[2][4];
        ldsm4(af, aB + ((wm*16 + arow)*136 + k16 + acol)*2);
        #pragma unroll
        for (int p = 0; p < 2; p++)
            ldsm4t(bf4[p], bB + ((k16 + (lane & 15))*72 + wn*32 + p*16 + ((lane >> 4) << 3))*2);
        #pragma unroll
        for (int nt = 0; nt < 4; nt++)
            mma_bf16(acc[nt], af, bf4[nt >> 1] + (nt & 1)*2);
    }
    __syncthreads();

    // fold attention mask bias into pl here: bias index = k = (row0 % 768) + m
    int kbase = (int)(row0 % 768);
    int r = wm*16 + (lane >> 2);
    float b_r  = g_bias[kbase + r];
    float b_r8 = g_bias[kbase + r + 8];
    __nv_bfloat16* sbout = spch;
    #pragma unroll
    for (int nt = 0; nt < 4; nt++){
        int c = wn*32 + nt*8 + 2*(lane & 3);
        sbout[(c  )*72 + r    ] = __float2bfloat16(acc[nt][0] + b_r);
        sbout[(c+1)*72 + r    ] = __float2bfloat16(acc[nt][1] + b_r);
        sbout[(c  )*72 + r + 8] = __float2bfloat16(acc[nt][2] + b_r8);
        sbout[(c+1)*72 + r + 8] = __float2bfloat16(acc[nt][3] + b_r8);
    }
    __syncthreads();
    for (int i = t; i < 512; i += 256){
        int col = i >> 3, m = (i & 7) * 8;
        *(uint4*)&g_pl[((long long)(nsb*64 + col))*NNSQ_ + row0 + m] =
            *(const uint4*)&sbout[col*72 + m];
    }
}

// ---------------- small kernels ----------------
__global__ void bias_k(const float* __restrict__ mask){
    int i = blockIdx.x * 256 + threadIdx.x;
    if (i < NN_) g_bias[i] = 1e9f * (mask[i] - 1.f);
}

__global__ void ln384_k(const float* __restrict__ in){
    int r = blockIdx.x, t = threadIdx.x;
    __shared__ float red[32];
    const float* p = in + (long long)r * CS_;
    float v0 = p[t], v1 = p[t+128], v2 = p[t+256];
    float s = blockReduce(v0+v1+v2, red, false);
    float m = s * (1.f/384.f);
    float d0 = v0-m, d1 = v1-m, d2 = v2-m;
    float q = blockReduce(d0*d0+d1*d1+d2*d2, red, false);
    float rstd = rsqrtf(q * (1.f/384.f) + 1e-5f);
    float* o = g_lnsc + (long long)r * CS_;
    o[t] = d0*rstd; o[t+128] = d1*rstd; o[t+256] = d2*rstd;
}

__global__ void cn_k(const float* __restrict__ aln, const float* __restrict__ fln){
    int i = blockIdx.x * 256 + threadIdx.x;
    if (i >= LL_*NN_*CS_) return;
    int l = i / (NN_*CS_);
    int rem = i % (NN_*CS_);
    int c = rem % CS_;
    float b = g_lnsc[rem];
    g_cnA[i] = b * aln[l*CS_ + c];
    g_cnF[i] = b * fln[l*CS_ + c];
}

__global__ void modulate_k(const float* __restrict__ a, const float* __restrict__ sig,
                           const float* __restrict__ add, __nv_bfloat16* __restrict__ xo){
    int r = blockIdx.x, t = threadIdx.x;
    __shared__ float red[32];
    const float* ar = a + (long long)r * 768;
    float v0 = ar[t], v1 = ar[t+256], v2 = ar[t+512];
    float s = blockReduce(v0+v1+v2, red, false);
    float m = s * (1.f/768.f);
    float d0 = v0-m, d1 = v1-m, d2 = v2-m;
    float q = blockReduce(d0*d0+d1*d1+d2*d2, red, false);
    float rstd = rsqrtf(q * (1.f/768.f) + 1e-5f);
    long long o = (long long)r * 768;
    xo[o+t]     = __float2bfloat16(sig[o+t]     * (d0*rstd) + add[o+t]);
    xo[o+t+256] = __float2bfloat16(sig[o+t+256] * (d1*rstd) + add[o+t+256]);
    xo[o+t+512] = __float2bfloat16(sig[o+t+512] * (d2*rstd) + add[o+t+512]);
}

__global__ void glu_k(){
    int i = blockIdx.x * 256 + threadIdx.x;
    if (i >= NN_*FF_/2) return;
    int n = i / (FF_/2), f = (i % (FF_/2)) * 2;
    const __nv_bfloat16* up = g_u + (long long)n*2*FF_;
    float2 u1 = __bfloat1622float2(*(const __nv_bfloat162*)&up[f]);
    float2 u2 = __bfloat1622float2(*(const __nv_bfloat162*)&up[FF_ + f]);
    float c0 = (u1.x/(1.f+__expf(-u1.x)))*u2.x;
    float c1 = (u1.y/(1.f+__expf(-u1.y)))*u2.y;
    *(unsigned*)&g_c[(long long)n*FF_ + f] = f2bf2(c0, c1);
}

// ---------------- host ----------------
extern "C" void kernel_launch(void* const* d_in, const int* in_sizes, int n_in,
                              void* d_out, int out_size)
{
    const float* act         = (const float*)d_in[0];
    const float* mask        = (const float*)d_in[1];
    const float* single_cond = (const float*)d_in[2];
    const float* pair_cond   = (const float*)d_in[3];
    const float* attn_cln    = (const float*)d_in[4];
    const float* attn_cs_w   = (const float*)d_in[5];
    const float* attn_cs_b   = (const float*)d_in[6];
    const float* attn_cb_w   = (const float*)d_in[7];
    const float* q_w         = (const float*)d_in[8];
    const float* q_b         = (const float*)d_in[9];
    const float* k_w         = (const float*)d_in[10];
    const float* v_w         = (const float*)d_in[11];
    const float* gate_w      = (const float*)d_in[12];
    const float* gate_b      = (const float*)d_in[13];
    const float* out_w       = (const float*)d_in[14];
    const float* attn_azc_w  = (const float*)d_in[15];
    const float* attn_azc_b  = (const float*)d_in[16];
    const float* ffw_cln     = (const float*)d_in[17];
    const float* ffw_cs_w    = (const float*)d_in[18];
    const float* ffw_cs_b    = (const float*)d_in[19];
    const float* ffw_cb_w    = (const float*)d_in[20];
    const float* t1_w        = (const float*)d_in[21];
    const float* t2_w        = (const float*)d_in[22];
    const float* ffw_azc_w   = (const float*)d_in[23];
    const float* ffw_azc_b   = (const float*)d_in[24];
    const float* pair_lns    = (const float*)d_in[25];
    const float* pair_w      = (const float*)d_in[26];
    float* a = (float*)d_out;

    __nv_bfloat16 *pl, *x, *qb, *kb, *vb, *gb, *wab, *cb, *ub;
    float *cnA, *cnF, *sigA, *addA, *azcA, *sigF, *addF, *azcF;
    cudaGetSymbolAddress((void**)&pl,   g_pl);
    cudaGetSymbolAddress((void**)&x,    g_x);
    cudaGetSymbolAddress((void**)&qb,   g_q);
    cudaGetSymbolAddress((void**)&kb,   g_k);
    cudaGetSymbolAddress((void**)&vb,   g_v);
    cudaGetSymbolAddress((void**)&gb,   g_gate);
    cudaGetSymbolAddress((void**)&wab,  g_wa);
    cudaGetSymbolAddress((void**)&cb,   g_c);
    cudaGetSymbolAddress((void**)&ub,   g_u);
    cudaGetSymbolAddress((void**)&cnA,  g_cnA);
    cudaGetSymbolAddress((void**)&cnF,  g_cnF);
    cudaGetSymbolAddress((void**)&sigA, g_sigA);
    cudaGetSymbolAddress((void**)&addA, g_addA);
    cudaGetSymbolAddress((void**)&azcA, g_azcA);
    cudaGetSymbolAddress((void**)&sigF, g_sigF);
    cudaGetSymbolAddress((void**)&addF, g_addF);
    cudaGetSymbolAddress((void**)&azcF, g_azcF);

    cudaMemcpyAsync(a, act, (size_t)NC_ * sizeof(float), cudaMemcpyDeviceToDevice);

    bias_k<<<3, 256>>>(mask);
    ln384_k<<<NN_, 128>>>(single_cond);
    cn_k<<<(LL_*NN_*CS_ + 255)/256, 256>>>(attn_cln, ffw_cln);
    pwcvt_k<<<32, 256>>>(pair_w);

    pair_k<<<dim3(2, 9216), 256>>>(pair_cond, pair_lns);

    pre6_tc<<<dim3(12, 12, 48), 256>>>(cnA, cnF, single_cond,
        attn_cs_w, attn_cb_w, attn_azc_w, ffw_cs_w, ffw_cb_w, ffw_azc_w,
        sigA, addA, azcA, sigF, addF, azcF,
        attn_cs_b, attn_azc_b, ffw_cs_b, ffw_azc_b);

    cudaFuncSetAttribute(flash_k, cudaFuncAttributeMaxDynamicSharedMemorySize, 55296);

    for (int l = 0; l < 8; l++){
        long long oNC = (long long)l * NC_;
        modulate_k<<<768, 256>>>(a, sigA + oNC, addA + oNC, x);
        qkvg_tc<<<dim3(12, 12, 4), 256>>>(x,
            q_w + oNC, k_w + oNC, v_w + oNC, gate_w + oNC,
            qb, kb, vb, gb, q_b + l*768, gate_b + l*768);
        flash_k<<<dim3(16, 12, NSPLIT_), 256, 55296>>>(qb, kb, vb,
            pl + (long long)l * HH_ * NNSQ_);
        comb_k<<<768, 384>>>(gb, wab);
        gemm_tc<32,1,0><<<dim3(12, 24, 1), 256>>>(768, wab, 768, 0, out_w + oNC, 768, 0,
            a, 768, 0, 4, azcA + oNC, 0);
        modulate_k<<<768, 256>>>(a, sigF + oNC, addF + oNC, x);
        gemm_tc<64,1,1><<<dim3(48, 12, 1), 256>>>(768, x, 768, 0, t1_w + (long long)l*768*3072, 3072, 0,
            ub, 3072, 0, 0, (const float*)0, 0);
        glu_k<<<(NN_*FF_/2 + 255)/256, 256>>>();
        gemm_tc<32,1,0><<<dim3(12, 24, 1), 256>>>(1536, cb, 1536, 0, t2_w + (long long)l*1536*768, 768, 0,
            a, 768, 0, 4, azcF + oNC, 0);
    }
    (void)in_sizes; (void)n_in; (void)out_size;
}